// round 1
// baseline (speedup 1.0000x reference)
#include <cuda_runtime.h>
#include <math.h>

#define N_NODES 128000
#define F_IN    128
#define D_LAT   32
#define B_G     256
#define NPG     500
#define K_TOP   30
#define L_LAYERS 3
#define E_EDGES 2048000

// ---------------- device scratch (static, no allocation) ----------------
__device__ float g_ego [N_NODES * D_LAT];
__device__ float g_neig[N_NODES * D_LAT];
__device__ float g_out [N_NODES * D_LAT];
__device__ int   g_counts[N_NODES];
__device__ int   g_rowptr[N_NODES];
__device__ int   g_cursor[N_NODES];
__device__ int   g_bsums[256];
__device__ int   g_col[E_EDGES];

// ---------------- CSR build ----------------
__global__ void k_zero_counts() {
    int i = blockIdx.x * blockDim.x + threadIdx.x;
    if (i < N_NODES) g_counts[i] = 0;
}

__global__ void k_hist(const int* __restrict__ edst) {
    int e = blockIdx.x * blockDim.x + threadIdx.x;
    if (e < E_EDGES) atomicAdd(&g_counts[edst[e]], 1);
}

// block-level exclusive scan (1024/block, 125 blocks exactly)
__global__ void k_scan1() {
    __shared__ int s[1024];
    int tid = threadIdx.x;
    int gid = blockIdx.x * 1024 + tid;
    int v = g_counts[gid];
    s[tid] = v;
    __syncthreads();
    #pragma unroll
    for (int off = 1; off < 1024; off <<= 1) {
        int t = (tid >= off) ? s[tid - off] : 0;
        __syncthreads();
        s[tid] += t;
        __syncthreads();
    }
    g_rowptr[gid] = s[tid] - v;          // exclusive within block
    if (tid == 1023) g_bsums[blockIdx.x] = s[1023];
}

__global__ void k_scan2() {
    if (threadIdx.x == 0 && blockIdx.x == 0) {
        int run = 0;
        for (int i = 0; i < 125; i++) {
            int t = g_bsums[i];
            g_bsums[i] = run;
            run += t;
        }
    }
}

__global__ void k_addoff() {
    int gid = blockIdx.x * 1024 + threadIdx.x;
    int rp = g_rowptr[gid] + g_bsums[gid >> 10];
    g_rowptr[gid] = rp;
    g_cursor[gid] = rp;
}

__global__ void k_scatter(const int* __restrict__ esrc, const int* __restrict__ edst) {
    int e = blockIdx.x * blockDim.x + threadIdx.x;
    if (e < E_EDGES) {
        int d = edst[e];
        int p = atomicAdd(&g_cursor[d], 1);
        g_col[p] = esrc[e];
    }
}

// ---------------- ego MLP: ego = relu(X@w0a+b0a)@w0b+b0b ; out = a0*ego ----
// warp per 4 rows; lane = output channel (D=32). w0a in smem, w0b in regs.
__global__ void k_mlp0(const float* __restrict__ X,
                       const float* __restrict__ w0a, const float* __restrict__ b0a,
                       const float* __restrict__ w0b, const float* __restrict__ b0b,
                       const float* __restrict__ alpha) {
    __shared__ float ws[F_IN * D_LAT];           // 16 KB
    int tid = threadIdx.x;
    for (int i = tid; i < F_IN * D_LAT; i += blockDim.x) ws[i] = w0a[i];
    int lane = tid & 31;
    float wb[32];
    #pragma unroll
    for (int j = 0; j < 32; j++) wb[j] = w0b[j * 32 + lane];
    float b0 = b0a[lane], b1 = b0b[lane], a0 = alpha[0];
    __syncthreads();

    int warp = (blockIdx.x * blockDim.x + tid) >> 5;
    int rbase = warp * 4;                         // 4000 blocks * 8 warps * 4 rows

    float x[4][4];
    #pragma unroll
    for (int rr = 0; rr < 4; rr++) {
        int row = rbase + rr;
        #pragma unroll
        for (int q = 0; q < 4; q++)
            x[rr][q] = X[row * F_IN + q * 32 + lane];
    }
    float acc[4] = {b0, b0, b0, b0};
    #pragma unroll
    for (int k = 0; k < F_IN; k++) {
        float w = ws[k * 32 + lane];
        #pragma unroll
        for (int rr = 0; rr < 4; rr++) {
            float xv = __shfl_sync(0xFFFFFFFFu, x[rr][k >> 5], k & 31);
            acc[rr] = fmaf(xv, w, acc[rr]);
        }
    }
    float h[4], o[4];
    #pragma unroll
    for (int rr = 0; rr < 4; rr++) { h[rr] = fmaxf(acc[rr], 0.f); o[rr] = b1; }
    #pragma unroll
    for (int j = 0; j < 32; j++) {
        #pragma unroll
        for (int rr = 0; rr < 4; rr++) {
            float hv = __shfl_sync(0xFFFFFFFFu, h[rr], j);
            o[rr] = fmaf(hv, wb[j], o[rr]);
        }
    }
    #pragma unroll
    for (int rr = 0; rr < 4; rr++) {
        int row = rbase + rr;
        g_ego[row * 32 + lane] = o[rr];
        g_out[row * 32 + lane] = a0 * o[rr];
    }
}

// ---------------- SpMM: neig[d] = sum_{edges into d} ego[src] --------------
// one warp per node; lane = channel. ego rows are 128B => one coalesced line.
__global__ void k_spmm() {
    int warp = (blockIdx.x * blockDim.x + threadIdx.x) >> 5;
    int lane = threadIdx.x & 31;
    if (warp >= N_NODES) return;
    int start = g_rowptr[warp];
    int cnt   = g_counts[warp];
    int end   = start + cnt;
    float a0 = 0.f, a1 = 0.f, a2 = 0.f, a3 = 0.f;
    int e = start;
    for (; e + 3 < end; e += 4) {
        int s0 = g_col[e], s1 = g_col[e + 1], s2 = g_col[e + 2], s3 = g_col[e + 3];
        a0 += g_ego[s0 * 32 + lane];
        a1 += g_ego[s1 * 32 + lane];
        a2 += g_ego[s2 * 32 + lane];
        a3 += g_ego[s3 * 32 + lane];
    }
    for (; e < end; e++) a0 += g_ego[g_col[e] * 32 + lane];
    g_neig[warp * 32 + lane] = (a0 + a1) + (a2 + a3);
}

// ---------------- layer MLP (concat folded into combined weights) ----------
// h = relu(ego@(Wa0+Wa2) + neig@(Wa1+Wa2) + ba) ; ego' = h@Wb + bb
// out += alpha[l+1]*ego'.  Warp per row, lane = channel, weights in registers.
__global__ void k_mlp1(const float* __restrict__ W1a, const float* __restrict__ B1a,
                       const float* __restrict__ W1b, const float* __restrict__ B1b,
                       const float* __restrict__ alpha, int l) {
    int lane = threadIdx.x & 31;
    const float* Wa = W1a + l * 96 * 32;
    const float* Wb = W1b + l * 32 * 32;
    float wea[32], wna[32], wb[32];
    #pragma unroll
    for (int j = 0; j < 32; j++) {
        float wc = Wa[(64 + j) * 32 + lane];
        wea[j] = Wa[j * 32 + lane] + wc;
        wna[j] = Wa[(32 + j) * 32 + lane] + wc;
        wb[j]  = Wb[j * 32 + lane];
    }
    float ba = B1a[l * 32 + lane], bb = B1b[l * 32 + lane], av = alpha[l + 1];

    int warp   = (blockIdx.x * blockDim.x + threadIdx.x) >> 5;
    int nwarps = (gridDim.x * blockDim.x) >> 5;

    for (int row = warp; row < N_NODES; row += nwarps) {
        float ev = g_ego [row * 32 + lane];
        float nv = g_neig[row * 32 + lane];
        float acce = ba, accn = 0.f;
        #pragma unroll
        for (int j = 0; j < 32; j++) {
            float e = __shfl_sync(0xFFFFFFFFu, ev, j);
            float n = __shfl_sync(0xFFFFFFFFu, nv, j);
            acce = fmaf(e, wea[j], acce);
            accn = fmaf(n, wna[j], accn);
        }
        float h = fmaxf(acce + accn, 0.f);
        float o = bb;
        #pragma unroll
        for (int j = 0; j < 32; j++) {
            float hv = __shfl_sync(0xFFFFFFFFu, h, j);
            o = fmaf(hv, wb[j], o);
        }
        g_ego[row * 32 + lane] = o;
        g_out[row * 32 + lane] += av * o;
    }
}

// ---------------- per-graph top-K sort pooling -----------------------------
// wl = final ego[:,31]; select K largest (desc, ties -> lower index),
// gather out rows, relu, write [B, K*D].
__global__ void k_topk(float* __restrict__ dout) {
    __shared__ float sv[512];
    __shared__ int   si[512];
    __shared__ float rv[512];
    __shared__ int   ri[512];
    __shared__ int   sel[K_TOP];
    int g = blockIdx.x, tid = threadIdx.x;     // 256 threads

    for (int i = tid; i < 512; i += 256) {
        if (i < NPG) { sv[i] = g_ego[(g * NPG + i) * 32 + 31]; si[i] = i; }
        else         { sv[i] = -3.402823466e38f;               si[i] = i; }
    }
    __syncthreads();

    for (int r = 0; r < K_TOP; r++) {
        for (int i = tid; i < 512; i += 256) { rv[i] = sv[i]; ri[i] = si[i]; }
        __syncthreads();
        for (int s = 256; s >= 1; s >>= 1) {
            if (tid < s) {
                float v1 = rv[tid], v2 = rv[tid + s];
                int   i1 = ri[tid], i2 = ri[tid + s];
                if (v2 > v1 || (v2 == v1 && i2 < i1)) { rv[tid] = v2; ri[tid] = i2; }
            }
            __syncthreads();
        }
        if (tid == 0) {
            int best = ri[0];
            sel[r] = best;
            sv[best] = -3.402823466e38f;       // remove from candidates
        }
        __syncthreads();
    }

    for (int i = tid; i < K_TOP * 32; i += 256) {
        int r = i >> 5, c = i & 31;
        int node = g * NPG + sel[r];
        float v = g_out[node * 32 + c];
        dout[g * (K_TOP * 32) + i] = fmaxf(v, 0.f);
    }
}

// ---------------- launch -----------------------------------------------
extern "C" void kernel_launch(void* const* d_in, const int* in_sizes, int n_in,
                              void* d_out, int out_size) {
    const float* node_feat = (const float*)d_in[0];
    const float* alpha     = (const float*)d_in[1];
    const float* w0a       = (const float*)d_in[2];
    const float* b0a       = (const float*)d_in[3];
    const float* w0b       = (const float*)d_in[4];
    const float* b0b       = (const float*)d_in[5];
    const float* W1a       = (const float*)d_in[6];
    const float* B1a       = (const float*)d_in[7];
    const float* W1b       = (const float*)d_in[8];
    const float* B1b       = (const float*)d_in[9];
    const int*   esrc      = (const int*)d_in[10];
    const int*   edst      = (const int*)d_in[11];
    float*       dout      = (float*)d_out;

    // CSR build (once per call; reused by all 3 SpMMs)
    k_zero_counts<<<125, 1024>>>();
    k_hist<<<E_EDGES / 256, 256>>>(edst);
    k_scan1<<<125, 1024>>>();
    k_scan2<<<1, 32>>>();
    k_addoff<<<125, 1024>>>();
    k_scatter<<<E_EDGES / 256, 256>>>(esrc, edst);

    // ego MLP + out init
    k_mlp0<<<4000, 256>>>(node_feat, w0a, b0a, w0b, b0b, alpha);

    // 3 GNN layers
    for (int l = 0; l < L_LAYERS; l++) {
        k_spmm<<<16000, 256>>>();
        k_mlp1<<<2000, 256>>>(W1a, B1a, W1b, B1b, alpha, l);
    }

    // sort pooling
    k_topk<<<B_G, 256>>>(dout);
}

// round 2
// speedup vs baseline: 1.1383x; 1.1383x over previous
#include <cuda_runtime.h>
#include <math.h>

#define N_NODES 128000
#define F_IN    128
#define D_LAT   32
#define B_G     256
#define NPG     500
#define K_TOP   30
#define L_LAYERS 3
#define E_EDGES 2048000

// ---------------- device scratch (static, no allocation) ----------------
__device__ float g_ego [N_NODES * D_LAT];
__device__ float g_neig[N_NODES * D_LAT];
__device__ float g_out [N_NODES * D_LAT];
__device__ int   g_counts[N_NODES];
__device__ int   g_rowptr[N_NODES];
__device__ int   g_cursor[N_NODES];
__device__ int   g_bsums[256];
__device__ int   g_col[E_EDGES];

// ---------------- CSR build ----------------
__global__ void k_zero_counts() {
    int i = blockIdx.x * blockDim.x + threadIdx.x;
    if (i < N_NODES) g_counts[i] = 0;
}

__global__ void k_hist(const int4* __restrict__ edst4) {
    int i = blockIdx.x * blockDim.x + threadIdx.x;   // E/4 threads
    int4 v = edst4[i];
    atomicAdd(&g_counts[v.x], 1);
    atomicAdd(&g_counts[v.y], 1);
    atomicAdd(&g_counts[v.z], 1);
    atomicAdd(&g_counts[v.w], 1);
}

// block-level exclusive scan (1024/block, 125 blocks exactly)
__global__ void k_scan1() {
    __shared__ int s[1024];
    int tid = threadIdx.x;
    int gid = blockIdx.x * 1024 + tid;
    int v = g_counts[gid];
    s[tid] = v;
    __syncthreads();
    #pragma unroll
    for (int off = 1; off < 1024; off <<= 1) {
        int t = (tid >= off) ? s[tid - off] : 0;
        __syncthreads();
        s[tid] += t;
        __syncthreads();
    }
    g_rowptr[gid] = s[tid] - v;          // exclusive within block
    if (tid == 1023) g_bsums[blockIdx.x] = s[1023];
}

// parallel scan of the 125 block sums (one 128-thread block)
__global__ void k_scan2() {
    __shared__ int wsum[4];
    int tid = threadIdx.x;
    int v = (tid < 125) ? g_bsums[tid] : 0;
    int x = v;
    #pragma unroll
    for (int off = 1; off < 32; off <<= 1) {
        int t = __shfl_up_sync(0xFFFFFFFFu, x, off);
        if ((tid & 31) >= off) x += t;
    }
    if ((tid & 31) == 31) wsum[tid >> 5] = x;
    __syncthreads();
    int base = 0;
    #pragma unroll
    for (int k = 0; k < 4; k++) if (k < (tid >> 5)) base += wsum[k];
    if (tid < 125) g_bsums[tid] = base + x - v;   // exclusive
}

__global__ void k_addoff() {
    int gid = blockIdx.x * 1024 + threadIdx.x;
    int rp = g_rowptr[gid] + g_bsums[gid >> 10];
    g_rowptr[gid] = rp;
    g_cursor[gid] = rp;
}

__global__ void k_scatter(const int4* __restrict__ esrc4, const int4* __restrict__ edst4) {
    int i = blockIdx.x * blockDim.x + threadIdx.x;   // E/4 threads
    int4 s = esrc4[i];
    int4 d = edst4[i];
    int p;
    p = atomicAdd(&g_cursor[d.x], 1); g_col[p] = s.x;
    p = atomicAdd(&g_cursor[d.y], 1); g_col[p] = s.y;
    p = atomicAdd(&g_cursor[d.z], 1); g_col[p] = s.z;
    p = atomicAdd(&g_cursor[d.w], 1); g_col[p] = s.w;
}

// ---------------- ego MLP: ego = relu(X@w0a+b0a)@w0b+b0b ; out = a0*ego ----
// warp per 4 rows; lane = output channel. Broadcasts via smem (no shfl).
__global__ void __launch_bounds__(256) k_mlp0(
        const float* __restrict__ X,
        const float* __restrict__ w0a, const float* __restrict__ b0a,
        const float* __restrict__ w0b, const float* __restrict__ b0b,
        const float* __restrict__ alpha) {
    __shared__ float ws[F_IN * D_LAT];          // w0a [k][lane], 16KB
    __shared__ float sx[8 * 512];               // 4 rows x 128 floats per warp, 16KB
    int tid  = threadIdx.x;
    int lane = tid & 31;
    int w    = tid >> 5;

    for (int i = tid; i < F_IN * D_LAT; i += 256) ws[i] = w0a[i];
    float wb[32];
    #pragma unroll
    for (int j = 0; j < 32; j++) wb[j] = w0b[j * 32 + lane];
    float b0 = b0a[lane], b1 = b0b[lane], a0 = alpha[0];
    __syncthreads();

    int warp  = blockIdx.x * 8 + w;
    int rbase = warp * 4;
    float* xw = &sx[w * 512];

    // stage 4 input rows into smem (coalesced float4 loads)
    #pragma unroll
    for (int rr = 0; rr < 4; rr++) {
        float4 v = *(const float4*)&X[(rbase + rr) * F_IN + lane * 4];
        *(float4*)&xw[rr * 128 + lane * 4] = v;
    }
    __syncwarp();

    // layer 1: acc[row][partial]
    float a[4][4];
    #pragma unroll
    for (int rr = 0; rr < 4; rr++) {
        a[rr][0] = b0; a[rr][1] = 0.f; a[rr][2] = 0.f; a[rr][3] = 0.f;
    }
    #pragma unroll 8
    for (int k = 0; k < F_IN; k += 4) {
        float w0 = ws[(k + 0) * 32 + lane];
        float w1 = ws[(k + 1) * 32 + lane];
        float w2 = ws[(k + 2) * 32 + lane];
        float w3 = ws[(k + 3) * 32 + lane];
        #pragma unroll
        for (int rr = 0; rr < 4; rr++) {
            float4 x4 = *(const float4*)&xw[rr * 128 + k];
            a[rr][0] = fmaf(x4.x, w0, a[rr][0]);
            a[rr][1] = fmaf(x4.y, w1, a[rr][1]);
            a[rr][2] = fmaf(x4.z, w2, a[rr][2]);
            a[rr][3] = fmaf(x4.w, w3, a[rr][3]);
        }
    }
    float h[4];
    #pragma unroll
    for (int rr = 0; rr < 4; rr++)
        h[rr] = fmaxf((a[rr][0] + a[rr][1]) + (a[rr][2] + a[rr][3]), 0.f);

    // layer 2: broadcast h via smem
    __syncwarp();
    #pragma unroll
    for (int rr = 0; rr < 4; rr++) xw[rr * 32 + lane] = h[rr];
    __syncwarp();

    float o[4][4];
    #pragma unroll
    for (int rr = 0; rr < 4; rr++) {
        o[rr][0] = b1; o[rr][1] = 0.f; o[rr][2] = 0.f; o[rr][3] = 0.f;
    }
    #pragma unroll
    for (int j = 0; j < 32; j += 4) {
        #pragma unroll
        for (int rr = 0; rr < 4; rr++) {
            float4 h4 = *(const float4*)&xw[rr * 32 + j];
            o[rr][0] = fmaf(h4.x, wb[j + 0], o[rr][0]);
            o[rr][1] = fmaf(h4.y, wb[j + 1], o[rr][1]);
            o[rr][2] = fmaf(h4.z, wb[j + 2], o[rr][2]);
            o[rr][3] = fmaf(h4.w, wb[j + 3], o[rr][3]);
        }
    }
    #pragma unroll
    for (int rr = 0; rr < 4; rr++) {
        int row = rbase + rr;
        float ov = (o[rr][0] + o[rr][1]) + (o[rr][2] + o[rr][3]);
        g_ego[row * 32 + lane] = ov;
        g_out[row * 32 + lane] = a0 * ov;
    }
}

// ---------------- SpMM: neig[d] = sum_{edges into d} ego[src] --------------
// one warp per node; lane = channel. 8-way unrolled gather for MLP.
__global__ void k_spmm() {
    int warp = (blockIdx.x * blockDim.x + threadIdx.x) >> 5;
    int lane = threadIdx.x & 31;
    if (warp >= N_NODES) return;
    int start = g_rowptr[warp];
    int end   = start + g_counts[warp];
    float a0 = 0.f, a1 = 0.f, a2 = 0.f, a3 = 0.f;
    float a4 = 0.f, a5 = 0.f, a6 = 0.f, a7 = 0.f;
    int e = start;
    for (; e + 7 < end; e += 8) {
        int s0 = g_col[e + 0], s1 = g_col[e + 1], s2 = g_col[e + 2], s3 = g_col[e + 3];
        int s4 = g_col[e + 4], s5 = g_col[e + 5], s6 = g_col[e + 6], s7 = g_col[e + 7];
        a0 += g_ego[s0 * 32 + lane];
        a1 += g_ego[s1 * 32 + lane];
        a2 += g_ego[s2 * 32 + lane];
        a3 += g_ego[s3 * 32 + lane];
        a4 += g_ego[s4 * 32 + lane];
        a5 += g_ego[s5 * 32 + lane];
        a6 += g_ego[s6 * 32 + lane];
        a7 += g_ego[s7 * 32 + lane];
    }
    for (; e + 3 < end; e += 4) {
        int s0 = g_col[e + 0], s1 = g_col[e + 1], s2 = g_col[e + 2], s3 = g_col[e + 3];
        a0 += g_ego[s0 * 32 + lane];
        a1 += g_ego[s1 * 32 + lane];
        a2 += g_ego[s2 * 32 + lane];
        a3 += g_ego[s3 * 32 + lane];
    }
    for (; e < end; e++) a0 += g_ego[g_col[e] * 32 + lane];
    g_neig[warp * 32 + lane] = ((a0 + a1) + (a2 + a3)) + ((a4 + a5) + (a6 + a7));
}

// ---------------- layer MLP (concat folded into combined weights) ----------
// h = relu(ego@(Wa0+Wa2) + neig@(Wa1+Wa2) + ba) ; ego' = h@Wb + bb
// out += alpha[l+1]*ego'.  Warp per row, smem broadcast (no shfl), weights in regs.
__global__ void __launch_bounds__(256) k_mlp1(
        const float* __restrict__ W1a, const float* __restrict__ B1a,
        const float* __restrict__ W1b, const float* __restrict__ B1b,
        const float* __restrict__ alpha, int l) {
    __shared__ float sm[8 * 96];                 // per-warp: ev[32], nv[32], h[32]
    int tid  = threadIdx.x;
    int lane = tid & 31;
    float* sw = &sm[(tid >> 5) * 96];

    const float* Wa = W1a + l * 96 * 32;
    const float* Wb = W1b + l * 32 * 32;
    float wea[32], wna[32], wb[32];
    #pragma unroll
    for (int j = 0; j < 32; j++) {
        float wc = Wa[(64 + j) * 32 + lane];
        wea[j] = Wa[j * 32 + lane] + wc;
        wna[j] = Wa[(32 + j) * 32 + lane] + wc;
        wb[j]  = Wb[j * 32 + lane];
    }
    float ba = B1a[l * 32 + lane], bb = B1b[l * 32 + lane], av = alpha[l + 1];

    int warp   = (blockIdx.x * 256 + tid) >> 5;
    int nwarps = (gridDim.x * 256) >> 5;

    for (int row = warp; row < N_NODES; row += nwarps) {
        float ev = g_ego [row * 32 + lane];
        float nv = g_neig[row * 32 + lane];
        sw[lane]      = ev;
        sw[32 + lane] = nv;
        __syncwarp();

        float e0 = ba, e1 = 0.f, e2 = 0.f, e3 = 0.f;
        float n0 = 0.f, n1 = 0.f, n2 = 0.f, n3 = 0.f;
        #pragma unroll
        for (int j = 0; j < 32; j += 4) {
            float4 e4 = *(const float4*)&sw[j];
            float4 n4 = *(const float4*)&sw[32 + j];
            e0 = fmaf(e4.x, wea[j + 0], e0);
            e1 = fmaf(e4.y, wea[j + 1], e1);
            e2 = fmaf(e4.z, wea[j + 2], e2);
            e3 = fmaf(e4.w, wea[j + 3], e3);
            n0 = fmaf(n4.x, wna[j + 0], n0);
            n1 = fmaf(n4.y, wna[j + 1], n1);
            n2 = fmaf(n4.z, wna[j + 2], n2);
            n3 = fmaf(n4.w, wna[j + 3], n3);
        }
        float h = fmaxf(((e0 + e1) + (e2 + e3)) + ((n0 + n1) + (n2 + n3)), 0.f);
        sw[64 + lane] = h;
        __syncwarp();

        float o0 = bb, o1 = 0.f, o2 = 0.f, o3 = 0.f;
        #pragma unroll
        for (int j = 0; j < 32; j += 4) {
            float4 h4 = *(const float4*)&sw[64 + j];
            o0 = fmaf(h4.x, wb[j + 0], o0);
            o1 = fmaf(h4.y, wb[j + 1], o1);
            o2 = fmaf(h4.z, wb[j + 2], o2);
            o3 = fmaf(h4.w, wb[j + 3], o3);
        }
        float o = (o0 + o1) + (o2 + o3);
        g_ego[row * 32 + lane] = o;
        g_out[row * 32 + lane] += av * o;
        __syncwarp();   // sw fully consumed before next row overwrites it
    }
}

// ---------------- per-graph top-K sort pooling -----------------------------
__global__ void k_topk(float* __restrict__ dout) {
    __shared__ float sv[512];
    __shared__ int   si[512];
    __shared__ float rv[512];
    __shared__ int   ri[512];
    __shared__ int   sel[K_TOP];
    int g = blockIdx.x, tid = threadIdx.x;     // 256 threads

    for (int i = tid; i < 512; i += 256) {
        if (i < NPG) { sv[i] = g_ego[(g * NPG + i) * 32 + 31]; si[i] = i; }
        else         { sv[i] = -3.402823466e38f;               si[i] = i; }
    }
    __syncthreads();

    for (int r = 0; r < K_TOP; r++) {
        for (int i = tid; i < 512; i += 256) { rv[i] = sv[i]; ri[i] = si[i]; }
        __syncthreads();
        for (int s = 256; s >= 1; s >>= 1) {
            if (tid < s) {
                float v1 = rv[tid], v2 = rv[tid + s];
                int   i1 = ri[tid], i2 = ri[tid + s];
                if (v2 > v1 || (v2 == v1 && i2 < i1)) { rv[tid] = v2; ri[tid] = i2; }
            }
            __syncthreads();
        }
        if (tid == 0) {
            int best = ri[0];
            sel[r] = best;
            sv[best] = -3.402823466e38f;
        }
        __syncthreads();
    }

    for (int i = tid; i < K_TOP * 32; i += 256) {
        int r = i >> 5, c = i & 31;
        int node = g * NPG + sel[r];
        float v = g_out[node * 32 + c];
        dout[g * (K_TOP * 32) + i] = fmaxf(v, 0.f);
    }
}

// ---------------- launch -----------------------------------------------
extern "C" void kernel_launch(void* const* d_in, const int* in_sizes, int n_in,
                              void* d_out, int out_size) {
    const float* node_feat = (const float*)d_in[0];
    const float* alpha     = (const float*)d_in[1];
    const float* w0a       = (const float*)d_in[2];
    const float* b0a       = (const float*)d_in[3];
    const float* w0b       = (const float*)d_in[4];
    const float* b0b       = (const float*)d_in[5];
    const float* W1a       = (const float*)d_in[6];
    const float* B1a       = (const float*)d_in[7];
    const float* W1b       = (const float*)d_in[8];
    const float* B1b       = (const float*)d_in[9];
    const int*   esrc      = (const int*)d_in[10];
    const int*   edst      = (const int*)d_in[11];
    float*       dout      = (float*)d_out;

    // CSR build (reused by all 3 SpMMs)
    k_zero_counts<<<125, 1024>>>();
    k_hist<<<E_EDGES / 4 / 256, 256>>>((const int4*)edst);
    k_scan1<<<125, 1024>>>();
    k_scan2<<<1, 128>>>();
    k_addoff<<<125, 1024>>>();
    k_scatter<<<E_EDGES / 4 / 256, 256>>>((const int4*)esrc, (const int4*)edst);

    // ego MLP + out init
    k_mlp0<<<4000, 256>>>(node_feat, w0a, b0a, w0b, b0b, alpha);

    // 3 GNN layers
    for (int l = 0; l < L_LAYERS; l++) {
        k_spmm<<<16000, 256>>>();
        k_mlp1<<<2000, 256>>>(W1a, B1a, W1b, B1b, alpha, l);
    }

    // sort pooling
    k_topk<<<B_G, 256>>>(dout);
}